// round 3
// baseline (speedup 1.0000x reference)
#include <cuda_runtime.h>
#include <cstdint>

#define BB 16
#define NN 1024
#define DD 64
#define NHH 4
#define HDD 16
#define HH 256
#define WW 256

// ---------------- scratch (device globals: no runtime allocation) ----------
__device__ float g_Q[BB*NHH*NN*HDD];          // (b,h,n,j) 4MB
__device__ float g_K[BB*NHH*NN*HDD];          // 4MB
__device__ float g_V[BB*NHH*NN*HDD];          // 4MB
__device__ float g_PF[BB*NN*DD];              // patch means 4MB
__device__ float g_att[BB*NN*DD];             // pose-scaled attention out 4MB
__device__ float g_pose[BB*DD];               // 1 + pose_mod
__device__ float g_po[2*BB*NHH*NN*HDD];       // key-split partial outputs 8.4MB
__device__ float g_pl[2*BB*NHH*NN];           // key-split partial exp-sums

// ---------------- f32x2 packed helpers (sm_10x) -----------------------------
__device__ __forceinline__ unsigned long long pack2(float lo, float hi) {
    unsigned long long r;
    asm("mov.b64 %0, {%1,%2};" : "=l"(r) : "f"(lo), "f"(hi));
    return r;
}
__device__ __forceinline__ void unpack2(unsigned long long v, float& lo, float& hi) {
    asm("mov.b64 {%0,%1}, %2;" : "=f"(lo), "=f"(hi) : "l"(v));
}
__device__ __forceinline__ unsigned long long ffma2(unsigned long long a,
                                                    unsigned long long b,
                                                    unsigned long long c) {
    unsigned long long d;
    asm("fma.rn.f32x2 %0, %1, %2, %3;" : "=l"(d) : "l"(a), "l"(b), "l"(c));
    return d;
}
__device__ __forceinline__ float ex2f(float x) {
    float y;
    asm("ex2.approx.f32 %0, %1;" : "=f"(y) : "f"(x));
    return y;
}

// ---------------- K1: patch-mean gather (high occupancy, no smem) -----------
// Blocks [0,512): 32 points/block, warp = 4 points, lanes = channels.
// Blocks [512,528): pose_scale[b][d] = 1 + pose_embed@Wp + bp.
__global__ __launch_bounds__(256) void gather_kernel(
    const float* __restrict__ feat, const int* __restrict__ coords,
    const float* __restrict__ pe, const float* __restrict__ Wp,
    const float* __restrict__ bp)
{
    if (blockIdx.x >= 512) {            // ---- pose tail blocks ----
        int b = blockIdx.x - 512;
        int d = threadIdx.x;
        if (d < 64) {
            float s = bp[d];
            #pragma unroll 8
            for (int p = 0; p < 64; p++) s += pe[b*64 + p] * Wp[p*64 + d];
            g_pose[b*64 + d] = 1.0f + s;
        }
        return;
    }

    int t = threadIdx.x, w = t >> 5, l = t & 31;
    int gp0 = blockIdx.x * 32;
    int b   = gp0 >> 10;

    #pragma unroll
    for (int i = 0; i < 4; i++) {
        int gp = gp0 + w*4 + i;
        int y = __ldg(coords + gp*2 + 0);     // warp-uniform broadcast
        int x = __ldg(coords + gp*2 + 1);
        int s = x - 2;
        bool fast = (s >= 0) && (s <= 248);
        if (fast) {
            int a = s & ~3;
            int o = s - a;                     // 0..3 warp-uniform
            #pragma unroll
            for (int cp = 0; cp < 2; cp++) {
                int ch = l + 32*cp;
                const float* plane = feat + ((size_t)(b*64 + ch) << 16);
                float sum = 0.0f;
                #pragma unroll
                for (int dy = 0; dy < 5; dy++) {
                    int yy = y + dy - 2;
                    int yc = min(max(yy, 0), HH-1);
                    float m = (yy == yc) ? 1.0f : 0.0f;
                    const float4* row = (const float4*)(plane + yc*WW + a);
                    float4 r0 = __ldg(row);
                    float4 r1 = __ldg(row + 1);
                    // branch-free sliding 5-window sum
                    float w0 = r0.x + r0.y + r0.z + r0.w + r1.x;
                    float w1 = w0 - r0.x + r1.y;
                    float w2 = w1 - r0.y + r1.z;
                    float w3 = w2 - r0.z + r1.w;
                    float rs = (o == 0) ? w0 : (o == 1) ? w1 : (o == 2) ? w2 : w3;
                    sum = fmaf(m, rs, sum);
                }
                g_PF[(size_t)gp*64 + ch] = sum * 0.04f;
            }
        } else {
            #pragma unroll
            for (int cp = 0; cp < 2; cp++) {
                int ch = l + 32*cp;
                const float* plane = feat + ((size_t)(b*64 + ch) << 16);
                float sum = 0.0f;
                for (int dy = 0; dy < 5; dy++) {
                    int yy = y + dy - 2;
                    if (yy < 0 || yy >= HH) continue;
                    const float* row = plane + yy*WW;
                    #pragma unroll
                    for (int dx = 0; dx < 5; dx++) {
                        int xx = x + dx - 2;
                        if (xx >= 0 && xx < WW) sum += __ldg(row + xx);
                    }
                }
                g_PF[(size_t)gp*64 + ch] = sum * 0.04f;
            }
        }
    }
}

// ---------------- K2: Q/K/V projection ------------------------------------
__global__ __launch_bounds__(256) void projection_kernel(
    const float* __restrict__ desc,
    const float* __restrict__ Wq, const float* __restrict__ bq,
    const float* __restrict__ Wk, const float* __restrict__ bk,
    const float* __restrict__ Wv, const float* __restrict__ bv)
{
    __shared__ float pf[32*64];
    __shared__ float dsc[32*64];

    int t = threadIdx.x;
    int gp0 = blockIdx.x * 32;
    int b   = gp0 >> 10;
    int n0  = gp0 & 1023;

    const float4* dsrc = (const float4*)(desc + (size_t)gp0*64);
    const float4* psrc = (const float4*)(g_PF + (size_t)gp0*64);
    ((float4*)dsc)[t]       = dsrc[t];
    ((float4*)dsc)[t + 256] = dsrc[t + 256];
    ((float4*)pf)[t]        = psrc[t];
    ((float4*)pf)[t + 256]  = psrc[t + 256];
    __syncthreads();

    int c = t & 63;
    int pbase = t >> 6;
    float accq[8], acck[8], accv[8];
    float bqc = bq[c], bkc = bk[c], bvc = bv[c];
    #pragma unroll
    for (int i = 0; i < 8; i++) { accq[i]=bqc; acck[i]=bkc; accv[i]=bvc; }
    for (int k = 0; k < 64; k++) {
        float wq = __ldg(Wq + k*64 + c);
        float wk = __ldg(Wk + k*64 + c);
        float wv = __ldg(Wv + k*64 + c);
        #pragma unroll
        for (int i = 0; i < 8; i++) {
            int p = pbase + 4*i;
            float dv = dsc[p*64 + k];
            float pv = pf[p*64 + k];
            accq[i] += dv * wq;
            acck[i] += pv * wk;
            accv[i] += pv * wv;
        }
    }
    int h = c >> 4, j = c & 15;
    size_t base = (size_t)(b*NHH + h) * NN;
    #pragma unroll
    for (int i = 0; i < 8; i++) {
        int p = pbase + 4*i;
        size_t idx = (base + n0 + p) * HDD + j;
        g_Q[idx] = accq[i];
        g_K[idx] = acck[i];
        g_V[idx] = accv[i];
    }
}

// ---------------- K3: attention, key-split 2x512, 512 queries/block ---------
// grid (4, NH, B) = 256 blocks, 2 blocks/SM -> 32 warps/SM, single wave.
// Unnormalized partial output + exp-sum per key half; exact combine later.
extern __shared__ float sm_attn[];
__global__ __launch_bounds__(512, 2) void attn_kernel() {
    float* Ks = sm_attn;                 // 512 keys x 16
    float* Vs = sm_attn + 512*HDD;

    int t  = threadIdx.x;
    int qs = blockIdx.x & 1;
    int ks = blockIdx.x >> 1;
    int b  = blockIdx.z, h = blockIdx.y;
    size_t bh = (size_t)(b*NHH + h) * NN * HDD;

    const float4* Kg = (const float4*)(g_K + bh + (size_t)ks*512*HDD);
    const float4* Vg = (const float4*)(g_V + bh + (size_t)ks*512*HDD);
    float4* Ks4 = (float4*)Ks;
    float4* Vs4 = (float4*)Vs;
    #pragma unroll
    for (int i = 0; i < 4; i++) {
        Ks4[t + 512*i] = Kg[t + 512*i];
        Vs4[t + 512*i] = Vg[t + 512*i];
    }

    int n = qs*512 + t;
    const float4* qp = (const float4*)(g_Q + bh + (size_t)n*HDD);
    const float CSC = 0.25f * 1.4426950408889634f;   // 1/sqrt(hd) * log2(e)
    unsigned long long q[8];
    #pragma unroll
    for (int i = 0; i < 4; i++) {
        float4 qv = qp[i];
        q[2*i+0] = pack2(qv.x*CSC, qv.y*CSC);
        q[2*i+1] = pack2(qv.z*CSC, qv.w*CSC);
    }
    __syncthreads();

    unsigned long long o0=0ull,o1=0ull,o2=0ull,o3=0ull,o4=0ull,o5=0ull,o6=0ull,o7=0ull;
    float lsum = 0.0f;

    #pragma unroll 1
    for (int kk = 0; kk < 512; kk++) {
        const ulonglong2* kr = (const ulonglong2*)(Ks + kk*HDD);
        ulonglong2 ka = kr[0], kb = kr[1], kc = kr[2], kd = kr[3];
        unsigned long long aA = 0ull, aB = 0ull;
        aA = ffma2(q[0], ka.x, aA);  aB = ffma2(q[1], ka.y, aB);
        aA = ffma2(q[2], kb.x, aA);  aB = ffma2(q[3], kb.y, aB);
        aA = ffma2(q[4], kc.x, aA);  aB = ffma2(q[5], kc.y, aB);
        aA = ffma2(q[6], kd.x, aA);  aB = ffma2(q[7], kd.y, aB);
        float a0,a1,a2,a3;
        unpack2(aA, a0, a1);  unpack2(aB, a2, a3);
        float e = ex2f((a0+a1)+(a2+a3));
        lsum += e;
        unsigned long long ep = pack2(e, e);
        const ulonglong2* vr = (const ulonglong2*)(Vs + kk*HDD);
        ulonglong2 va = vr[0], vb = vr[1], vc = vr[2], vd = vr[3];
        o0 = ffma2(ep, va.x, o0);  o1 = ffma2(ep, va.y, o1);
        o2 = ffma2(ep, vb.x, o2);  o3 = ffma2(ep, vb.y, o3);
        o4 = ffma2(ep, vc.x, o4);  o5 = ffma2(ep, vc.y, o5);
        o6 = ffma2(ep, vd.x, o6);  o7 = ffma2(ep, vd.y, o7);
    }

    float oo[16];
    unpack2(o0, oo[0],  oo[1]);  unpack2(o1, oo[2],  oo[3]);
    unpack2(o2, oo[4],  oo[5]);  unpack2(o3, oo[6],  oo[7]);
    unpack2(o4, oo[8],  oo[9]);  unpack2(o5, oo[10], oo[11]);
    unpack2(o6, oo[12], oo[13]); unpack2(o7, oo[14], oo[15]);

    size_t pidx = ((size_t)ks*BB*NHH + b*NHH + h) * NN + n;
    float4* po = (float4*)(g_po + pidx*HDD);
    po[0] = make_float4(oo[0],  oo[1],  oo[2],  oo[3]);
    po[1] = make_float4(oo[4],  oo[5],  oo[6],  oo[7]);
    po[2] = make_float4(oo[8],  oo[9],  oo[10], oo[11]);
    po[3] = make_float4(oo[12], oo[13], oo[14], oo[15]);
    g_pl[pidx] = lsum;
}

// ---------------- K4: combine key-split partials + pose scale ---------------
__global__ __launch_bounds__(256) void reduce_kernel() {
    int idx = blockIdx.x*256 + threadIdx.x;     // = (b*NHH+h)*NN + n
    int b = idx >> 12;
    int h = (idx >> 10) & 3;
    int n = idx & 1023;

    size_t i0 = (size_t)idx * HDD;
    const float4* p0 = (const float4*)(g_po + i0);
    const float4* p1 = (const float4*)(g_po + (size_t)BB*NHH*NN*HDD + i0);
    float inv = 1.0f / (g_pl[idx] + g_pl[BB*NHH*NN + idx]);

    const float* ps = g_pose + b*64 + h*16;
    float* op = g_att + ((size_t)b*NN + n)*DD + h*16;
    #pragma unroll
    for (int j = 0; j < 4; j++) {
        float4 A = p0[j], B = p1[j];
        op[4*j+0] = (A.x + B.x) * inv * ps[4*j+0];
        op[4*j+1] = (A.y + B.y) * inv * ps[4*j+1];
        op[4*j+2] = (A.z + B.z) * inv * ps[4*j+2];
        op[4*j+3] = (A.w + B.w) * inv * ps[4*j+3];
    }
}

// ---------------- K5: out = g_att @ Wo + bo ---------------------------------
__global__ __launch_bounds__(256) void outproj_kernel(const float* __restrict__ Wo,
                                                      const float* __restrict__ bo,
                                                      float* __restrict__ out) {
    __shared__ float fat[64*64];
    int t = threadIdx.x;
    size_t rbase = (size_t)blockIdx.x * 64;
    const float4* src = (const float4*)(g_att + rbase*64);
    float4* dst = (float4*)fat;
    #pragma unroll
    for (int i = 0; i < 4; i++) dst[t + 256*i] = src[t + 256*i];
    __syncthreads();

    int c = t & 63, r0 = t >> 6;
    float acc[16];
    float bc = bo[c];
    #pragma unroll
    for (int i = 0; i < 16; i++) acc[i] = bc;
    #pragma unroll 4
    for (int k = 0; k < 64; k += 4) {
        float w0 = __ldg(Wo + (k+0)*64 + c);
        float w1 = __ldg(Wo + (k+1)*64 + c);
        float w2 = __ldg(Wo + (k+2)*64 + c);
        float w3 = __ldg(Wo + (k+3)*64 + c);
        #pragma unroll
        for (int i = 0; i < 16; i++) {
            float4 f = *(const float4*)&fat[(r0 + 4*i)*64 + k];
            acc[i] += f.x*w0 + f.y*w1 + f.z*w2 + f.w*w3;
        }
    }
    #pragma unroll
    for (int i = 0; i < 16; i++) out[(rbase + r0 + 4*i)*64 + c] = acc[i];
}

// ---------------- launch ----------------------------------------------------
extern "C" void kernel_launch(void* const* d_in, const int* in_sizes, int n_in,
                              void* d_out, int out_size) {
    const float* desc   = (const float*)d_in[0];
    const float* feat   = (const float*)d_in[1];
    const int*   coords = (const int*)  d_in[2];
    const float* pose   = (const float*)d_in[3];
    const float* Wq = (const float*)d_in[4];  const float* bq = (const float*)d_in[5];
    const float* Wk = (const float*)d_in[6];  const float* bk = (const float*)d_in[7];
    const float* Wv = (const float*)d_in[8];  const float* bv = (const float*)d_in[9];
    const float* Wp = (const float*)d_in[10]; const float* bp = (const float*)d_in[11];
    const float* Wo = (const float*)d_in[12]; const float* bo = (const float*)d_in[13];
    float* out = (float*)d_out;

    cudaFuncSetAttribute(attn_kernel, cudaFuncAttributeMaxDynamicSharedMemorySize,
                         2 * 512 * HDD * sizeof(float));

    gather_kernel<<<512 + BB, 256>>>(feat, coords, pose, Wp, bp);
    projection_kernel<<<512, 256>>>(desc, Wq, bq, Wk, bk, Wv, bv);
    attn_kernel<<<dim3(4, NHH, BB), 512, 2*512*HDD*sizeof(float)>>>();
    reduce_kernel<<<(BB*NHH*NN)/256, 256>>>();
    outproj_kernel<<<(BB*NN)/64, 256>>>(Wo, bo, out);
}

// round 5
// speedup vs baseline: 1.6943x; 1.6943x over previous
#include <cuda_runtime.h>
#include <cstdint>

#define BB 16
#define NN 1024
#define DD 64
#define NHH 4
#define HDD 16
#define HH 256
#define WW 256

// ---------------- scratch (device globals: no runtime allocation) ----------
__device__ float g_Q[BB*NHH*NN*HDD];          // (b,h,n,j) 4MB
__device__ float g_K[BB*NHH*NN*HDD];          // 4MB
__device__ float g_V[BB*NHH*NN*HDD];          // 4MB
__device__ float g_att[BB*NN*DD];             // pose-scaled attention out 4MB
__device__ float g_pose[BB*DD];               // 1 + pose_mod

// ---------------- helpers ---------------------------------------------------
__device__ __forceinline__ float ex2f(float x) {
    float y;
    asm("ex2.approx.f32 %0, %1;" : "=f"(y) : "f"(x));
    return y;
}
__device__ __forceinline__ uint32_t tf32cvt(float f) {
    uint32_t u;
    asm("cvt.rna.tf32.f32 %0, %1;" : "=r"(u) : "f"(f));
    return u;
}
__device__ __forceinline__ void mma_tf32(float& d0, float& d1, float& d2, float& d3,
                                         uint32_t a0, uint32_t a1, uint32_t a2, uint32_t a3,
                                         uint32_t b0, uint32_t b1) {
    asm("mma.sync.aligned.m16n8k8.row.col.f32.tf32.tf32.f32 "
        "{%0,%1,%2,%3}, {%4,%5,%6,%7}, {%8,%9}, {%0,%1,%2,%3};"
        : "+f"(d0), "+f"(d1), "+f"(d2), "+f"(d3)
        : "r"(a0), "r"(a1), "r"(a2), "r"(a3), "r"(b0), "r"(b1));
}

// ---------------- K1: patch-mean gather + Q/K/V projection (+pose tail) -----
__global__ __launch_bounds__(256) void gather_project_kernel(
    const float* __restrict__ desc, const float* __restrict__ feat,
    const int*   __restrict__ coords,
    const float* __restrict__ Wq, const float* __restrict__ bq,
    const float* __restrict__ Wk, const float* __restrict__ bk,
    const float* __restrict__ Wv, const float* __restrict__ bv,
    const float* __restrict__ pe, const float* __restrict__ Wp,
    const float* __restrict__ bp)
{
    if (blockIdx.x >= 512) {            // ---- pose tail blocks ----
        int b = blockIdx.x - 512;
        int d = threadIdx.x;
        if (d < 64) {
            float s = bp[d];
            #pragma unroll 8
            for (int p = 0; p < 64; p++) s += pe[b*64 + p] * Wp[p*64 + d];
            g_pose[b*64 + d] = 1.0f + s;
        }
        return;
    }

    __shared__ float pf[32][64];
    __shared__ float dsc[32][64];
    __shared__ int sy[32], sx[32];

    int t = threadIdx.x;
    int gp0 = blockIdx.x * 32;
    int b   = gp0 >> 10;
    int n0  = gp0 & 1023;

    if (t < 32) {
        sy[t] = coords[(gp0 + t)*2 + 0];
        sx[t] = coords[(gp0 + t)*2 + 1];
    }
    #pragma unroll
    for (int i = 0; i < 8; i++) {
        int o = t + 256*i;
        ((float*)dsc)[o] = desc[(size_t)gp0*64 + o];
    }
    __syncthreads();

    int w = t >> 5, l = t & 31;
    for (int i = 0; i < 4; i++) {
        int p = w*4 + i;
        int y = sy[p], x = sx[p];
        int s = x - 2;
        bool fast = (s >= 0) && (s <= 248);
        if (fast) {
            int a = s & ~3;
            int o = s - a;
            #pragma unroll
            for (int cp = 0; cp < 2; cp++) {
                int ch = l + 32*cp;
                const float* plane = feat + ((size_t)(b*64 + ch) << 16);
                float sum = 0.0f;
                #pragma unroll
                for (int dy = 0; dy < 5; dy++) {
                    int yy = y + dy - 2;
                    int yc = min(max(yy, 0), HH-1);
                    float m = (yy == yc) ? 1.0f : 0.0f;
                    const float4* row = (const float4*)(plane + yc*WW + a);
                    float4 r0 = __ldg(row);
                    float4 r1 = __ldg(row + 1);
                    float v0=r0.x, v1=r0.y, v2=r0.z, v3=r0.w;
                    float v4=r1.x, v5=r1.y, v6=r1.z, v7=r1.w;
                    float rs;
                    switch (o) {
                        case 0:  rs = v0+v1+v2+v3+v4; break;
                        case 1:  rs = v1+v2+v3+v4+v5; break;
                        case 2:  rs = v2+v3+v4+v5+v6; break;
                        default: rs = v3+v4+v5+v6+v7; break;
                    }
                    sum = fmaf(m, rs, sum);
                }
                pf[p][ch] = sum * 0.04f;
            }
        } else {
            #pragma unroll
            for (int cp = 0; cp < 2; cp++) {
                int ch = l + 32*cp;
                const float* plane = feat + ((size_t)(b*64 + ch) << 16);
                float sum = 0.0f;
                for (int dy = 0; dy < 5; dy++) {
                    int yy = y + dy - 2;
                    if (yy < 0 || yy >= HH) continue;
                    const float* row = plane + yy*WW;
                    #pragma unroll
                    for (int dx = 0; dx < 5; dx++) {
                        int xx = x + dx - 2;
                        if (xx >= 0 && xx < WW) sum += __ldg(row + xx);
                    }
                }
                pf[p][ch] = sum * 0.04f;
            }
        }
    }
    __syncthreads();

    int c = t & 63;
    int pbase = t >> 6;
    float accq[8], acck[8], accv[8];
    float bqc = bq[c], bkc = bk[c], bvc = bv[c];
    #pragma unroll
    for (int i = 0; i < 8; i++) { accq[i]=bqc; acck[i]=bkc; accv[i]=bvc; }
    for (int k = 0; k < 64; k++) {
        float wq = __ldg(Wq + k*64 + c);
        float wk = __ldg(Wk + k*64 + c);
        float wv = __ldg(Wv + k*64 + c);
        #pragma unroll
        for (int i = 0; i < 8; i++) {
            int p = pbase + 4*i;
            float dv = dsc[p][k];
            float pv = pf[p][k];
            accq[i] += dv * wq;
            acck[i] += pv * wk;
            accv[i] += pv * wv;
        }
    }
    int h = c >> 4, j = c & 15;
    size_t base = (size_t)(b*NHH + h) * NN;
    #pragma unroll
    for (int i = 0; i < 8; i++) {
        int p = pbase + 4*i;
        size_t idx = (base + n0 + p) * HDD + j;
        g_Q[idx] = accq[i];
        g_K[idx] = acck[i];
        g_V[idx] = accv[i];
    }
}

// ---------------- K2: all-tf32 tensor-core attention ------------------------
// CTA = 256 threads (8 warps), warp = 16 query rows -> 128 rows/CTA.
// grid (8, NH, B) = 512 CTAs. Key tiles of 64 streamed through smem.
// QK^T: m16n8k8 tf32. P.V: m16n8k8 tf32 with V key-rows PERMUTED in smem
// (key j -> row 4(j&1)+(j>>1) within each 8-block) so the QK D-fragment
// (cols {2t4,2t4+1}) is directly the PV A-fragment (cols {t4,t4+4}).
#define KPAD 20
#define VPAD 24
__global__ __launch_bounds__(256) void attn_mma_kernel() {
    __shared__ uint32_t Ks[64*KPAD];     // tf32 bits, [key][d] padded
    __shared__ uint32_t Vs[64*VPAD];     // tf32 bits, [perm key][d] padded

    int t = threadIdx.x;
    int w = t >> 5, lane = t & 31, g = lane >> 2, t4 = lane & 3;
    int b = blockIdx.z, h = blockIdx.y;
    size_t bh = (size_t)(b*NHH + h) * NN * HDD;
    const float* Kg = g_K + bh;
    const float* Vg = g_V + bh;

    int qrow = blockIdx.x*128 + w*16;
    const float* Qp = g_Q + bh + (size_t)qrow*HDD;
    const float CSC = 0.25f * 1.4426950408889634f;  // 1/sqrt(hd) * log2(e)

    uint32_t qa[2][4];
    #pragma unroll
    for (int c = 0; c < 2; c++) {
        qa[c][0] = tf32cvt(Qp[ g   *16 + c*8 + t4    ] * CSC);
        qa[c][1] = tf32cvt(Qp[(g+8)*16 + c*8 + t4    ] * CSC);
        qa[c][2] = tf32cvt(Qp[ g   *16 + c*8 + t4 + 4] * CSC);
        qa[c][3] = tf32cvt(Qp[(g+8)*16 + c*8 + t4 + 4] * CSC);
    }

    float o0[4] = {0,0,0,0};    // d cols 0-7
    float o1[4] = {0,0,0,0};    // d cols 8-15
    float rs0 = 0.0f, rs1 = 0.0f;

    int key = t >> 2, dc = t & 3;                       // loader roles
    int vrow = (key & ~7) + 4*(key & 1) + ((key & 7) >> 1);  // permuted V row

    // prefetch tile 0
    float4 kreg = ((const float4*)Kg)[t];
    float4 vreg = ((const float4*)Vg)[t];

    for (int tile = 0; tile < 16; tile++) {
        __syncthreads();   // previous compute done
        {
            uint32_t* kd = Ks + key*KPAD + dc*4;
            kd[0] = tf32cvt(kreg.x); kd[1] = tf32cvt(kreg.y);
            kd[2] = tf32cvt(kreg.z); kd[3] = tf32cvt(kreg.w);
            uint4 vv;
            vv.x = tf32cvt(vreg.x); vv.y = tf32cvt(vreg.y);
            vv.z = tf32cvt(vreg.z); vv.w = tf32cvt(vreg.w);
            *(uint4*)(Vs + vrow*VPAD + dc*4) = vv;
        }
        __syncthreads();
        if (tile < 15) {               // prefetch next tile
            kreg = ((const float4*)(Kg + (size_t)(tile+1)*64*16))[t];
            vreg = ((const float4*)(Vg + (size_t)(tile+1)*64*16))[t];
        }

        // per 8-key block: QK (2 mma) -> exp -> PV (2 mma), P layout reused
        #pragma unroll
        for (int j = 0; j < 8; j++) {
            float d0=0.f, d1=0.f, d2=0.f, d3=0.f;
            #pragma unroll
            for (int c = 0; c < 2; c++) {
                const uint32_t* kb = Ks + (j*8+g)*KPAD + c*8 + t4;
                mma_tf32(d0,d1,d2,d3, qa[c][0],qa[c][1],qa[c][2],qa[c][3],
                         kb[0], kb[4]);
            }
            float p0 = ex2f(d0), p1 = ex2f(d1), p2 = ex2f(d2), p3 = ex2f(d3);
            rs0 += p0 + p1;
            rs1 += p2 + p3;
            // A-frag: a0=row g col t4 (key 2t4)=p0, a1=row g+8 col t4=p2,
            //         a2=row g col t4+4 (key 2t4+1)=p1, a3=row g+8=p3
            uint32_t a0 = tf32cvt(p0), a1 = tf32cvt(p2);
            uint32_t a2 = tf32cvt(p1), a3 = tf32cvt(p3);
            uint32_t b00 = Vs[(j*8 + t4    )*VPAD + g    ];
            uint32_t b01 = Vs[(j*8 + t4 + 4)*VPAD + g    ];
            uint32_t b10 = Vs[(j*8 + t4    )*VPAD + g + 8];
            uint32_t b11 = Vs[(j*8 + t4 + 4)*VPAD + g + 8];
            mma_tf32(o0[0],o0[1],o0[2],o0[3], a0,a1,a2,a3, b00,b01);
            mma_tf32(o1[0],o1[1],o1[2],o1[3], a0,a1,a2,a3, b10,b11);
        }
    }

    // reduce row sums across quad (cols live on t4 lanes)
    rs0 += __shfl_xor_sync(0xffffffff, rs0, 1);
    rs0 += __shfl_xor_sync(0xffffffff, rs0, 2);
    rs1 += __shfl_xor_sync(0xffffffff, rs1, 1);
    rs1 += __shfl_xor_sync(0xffffffff, rs1, 2);
    float inv0 = 1.0f / rs0;
    float inv1 = 1.0f / rs1;

    const float* ps = g_pose + b*64 + h*16;
    size_t r0 = ((size_t)b*NN + qrow + g    )*64 + h*16;
    size_t r1 = ((size_t)b*NN + qrow + g + 8)*64 + h*16;
    #pragma unroll
    for (int nd = 0; nd < 2; nd++) {
        const float* o = nd ? o1 : o0;
        int cc = nd*8 + 2*t4;
        float p0 = ps[cc], p1 = ps[cc+1];
        *(float2*)&g_att[r0 + cc] = make_float2(o[0]*inv0*p0, o[1]*inv0*p1);
        *(float2*)&g_att[r1 + cc] = make_float2(o[2]*inv1*p0, o[3]*inv1*p1);
    }
}

// ---------------- K3: out = g_att @ Wo + bo ---------------------------------
__global__ __launch_bounds__(256) void outproj_kernel(const float* __restrict__ Wo,
                                                      const float* __restrict__ bo,
                                                      float* __restrict__ out) {
    __shared__ float fat[64*64];
    int t = threadIdx.x;
    size_t rbase = (size_t)blockIdx.x * 64;
    const float4* src = (const float4*)(g_att + rbase*64);
    float4* dst = (float4*)fat;
    #pragma unroll
    for (int i = 0; i < 4; i++) dst[t + 256*i] = src[t + 256*i];
    __syncthreads();

    int c = t & 63, r0 = t >> 6;
    float acc[16];
    float bc = bo[c];
    #pragma unroll
    for (int i = 0; i < 16; i++) acc[i] = bc;
    #pragma unroll 4
    for (int k = 0; k < 64; k += 4) {
        float w0 = __ldg(Wo + (k+0)*64 + c);
        float w1 = __ldg(Wo + (k+1)*64 + c);
        float w2 = __ldg(Wo + (k+2)*64 + c);
        float w3 = __ldg(Wo + (k+3)*64 + c);
        #pragma unroll
        for (int i = 0; i < 16; i++) {
            float4 f = *(const float4*)&fat[(r0 + 4*i)*64 + k];
            acc[i] += f.x*w0 + f.y*w1 + f.z*w2 + f.w*w3;
        }
    }
    #pragma unroll
    for (int i = 0; i < 16; i++) out[(rbase + r0 + 4*i)*64 + c] = acc[i];
}

// ---------------- launch ----------------------------------------------------
extern "C" void kernel_launch(void* const* d_in, const int* in_sizes, int n_in,
                              void* d_out, int out_size) {
    const float* desc   = (const float*)d_in[0];
    const float* feat   = (const float*)d_in[1];
    const int*   coords = (const int*)  d_in[2];
    const float* pose   = (const float*)d_in[3];
    const float* Wq = (const float*)d_in[4];  const float* bq = (const float*)d_in[5];
    const float* Wk = (const float*)d_in[6];  const float* bk = (const float*)d_in[7];
    const float* Wv = (const float*)d_in[8];  const float* bv = (const float*)d_in[9];
    const float* Wp = (const float*)d_in[10]; const float* bp = (const float*)d_in[11];
    const float* Wo = (const float*)d_in[12]; const float* bo = (const float*)d_in[13];
    float* out = (float*)d_out;

    gather_project_kernel<<<512 + BB, 256>>>(desc, feat, coords,
                                             Wq, bq, Wk, bk, Wv, bv,
                                             pose, Wp, bp);
    attn_mma_kernel<<<dim3(8, NHH, BB), 256>>>();
    outproj_kernel<<<(BB*NN)/64, 256>>>(Wo, bo, out);
}